// round 5
// baseline (speedup 1.0000x reference)
#include <cuda_runtime.h>
#include <cuda_fp16.h>
#include <cstdint>

// Problem dims
#define N_SAMPLES 2048
#define D_FEAT    64
#define P_PAIRS   2016
#define INNER     32
#define KDIM      64512   // P_PAIRS * INNER
#define HIDDEN    2048
#define CLASSES   10

// -------------------- scratch (device globals; no allocation) --------------------
__device__ __half g_u [(size_t)N_SAMPLES * KDIM];   // relu(pairs@Wu+bu), fp16, row-major [N, K]
__device__ __half g_bt[(size_t)HIDDEN    * KDIM];   // Wv^T fp16, K-major [HIDDEN, K]
__device__ float  g_v [(size_t)N_SAMPLES * HIDDEN]; // relu(u@Wv+bv)
__device__ float  g_xT[(size_t)D_FEAT * N_SAMPLES]; // x transposed

// -------------------- helpers --------------------
__device__ __forceinline__ uint32_t smem_u32(const void* p) {
    return (uint32_t)__cvta_generic_to_shared(p);
}
__device__ __forceinline__ void cp_async16(uint32_t dst, const void* src) {
    asm volatile("cp.async.cg.shared.global [%0], [%1], 16;" :: "r"(dst), "l"(src) : "memory");
}
__device__ __forceinline__ void cp_commit() {
    asm volatile("cp.async.commit_group;" ::: "memory");
}
template <int N>
__device__ __forceinline__ void cp_wait() {
    asm volatile("cp.async.wait_group %0;" :: "n"(N) : "memory");
}
__device__ __forceinline__ void ldsm_x4(uint32_t* r, uint32_t addr) {
    asm volatile("ldmatrix.sync.aligned.m8n8.x4.shared.b16 {%0,%1,%2,%3}, [%4];"
                 : "=r"(r[0]), "=r"(r[1]), "=r"(r[2]), "=r"(r[3]) : "r"(addr));
}
__device__ __forceinline__ void mma16816(float* c, const uint32_t* a, const uint32_t* b) {
    asm volatile(
        "mma.sync.aligned.m16n8k16.row.col.f32.f16.f16.f32 "
        "{%0,%1,%2,%3}, {%4,%5,%6,%7}, {%8,%9}, {%0,%1,%2,%3};"
        : "+f"(c[0]), "+f"(c[1]), "+f"(c[2]), "+f"(c[3])
        : "r"(a[0]), "r"(a[1]), "r"(a[2]), "r"(a[3]), "r"(b[0]), "r"(b[1]));
}

// ==================== kernel 1: transpose x ====================
__global__ void k_transpose_x(const float* __restrict__ x) {
    int idx = blockIdx.x * blockDim.x + threadIdx.x;
    if (idx < N_SAMPLES * D_FEAT) {
        int n = idx >> 6, d = idx & 63;
        g_xT[(size_t)d * N_SAMPLES + n] = x[idx];
    }
}

// ==================== kernel 2 (fused): pairwise MLP + Wv transpose/convert ====================
#define CONV_BLOCKS ((HIDDEN / 32) * (KDIM / 32))   // 64 * 2016

__global__ void k_prep(const float* __restrict__ Wu, const float* __restrict__ bu,
                       const float* __restrict__ Wv) {
    int tid = threadIdx.x;
    if (blockIdx.x < P_PAIRS) {
        int p = blockIdx.x;
        int a = 0, rem = p;
        while (rem >= (D_FEAT - 1 - a)) { rem -= (D_FEAT - 1 - a); a++; }
        int b = a + 1 + rem;

        __shared__ float w0[INNER], w1[INNER], bb[INNER];
        if (tid < INNER) {
            w0[tid] = Wu[(size_t)p * 2 * INNER + tid];
            w1[tid] = Wu[(size_t)p * 2 * INNER + INNER + tid];
            bb[tid] = bu[(size_t)p * INNER + tid];
        }
        __syncthreads();

        const float* xa = g_xT + (size_t)a * N_SAMPLES;
        const float* xb = g_xT + (size_t)b * N_SAMPLES;
        for (int n = tid; n < N_SAMPLES; n += blockDim.x) {
            float va = xa[n], vb = xb[n];
            __half2 outv[INNER / 2];
            #pragma unroll
            for (int i = 0; i < INNER; i += 2) {
                float r0 = fmaf(va, w0[i],     fmaf(vb, w1[i],     bb[i]));
                float r1 = fmaf(va, w0[i + 1], fmaf(vb, w1[i + 1], bb[i + 1]));
                outv[i / 2] = __floats2half2_rn(fmaxf(r0, 0.f), fmaxf(r1, 0.f));
            }
            uint4* dst = reinterpret_cast<uint4*>(g_u + (size_t)n * KDIM + (size_t)p * INNER);
            const uint4* src = reinterpret_cast<const uint4*>(outv);
            dst[0] = src[0]; dst[1] = src[1]; dst[2] = src[2]; dst[3] = src[3];
        }
    } else {
        int bid = blockIdx.x - P_PAIRS;
        int nt0 = (bid & 63) * 32;        // HIDDEN tile
        int kt0 = (bid >> 6) * 32;        // KDIM tile
        int tx = tid & 31, ty = tid >> 5; // 32 x 8
        __shared__ float tile[32][33];
        #pragma unroll
        for (int r = 0; r < 4; r++) {
            int k = kt0 + ty + r * 8;
            tile[ty + r * 8][tx] = Wv[(size_t)k * HIDDEN + nt0 + tx];
        }
        __syncthreads();
        #pragma unroll
        for (int r = 0; r < 4; r++) {
            int n = nt0 + ty + r * 8;
            g_bt[(size_t)n * KDIM + kt0 + tx] = __float2half(tile[tx][ty + r * 8]);
        }
    }
}

// ==================== kernel 3: big GEMM v = relu(u @ Wv + bv) via mma.sync ====================
// 2 CTAs per SM to desynchronize pipeline barriers: while one CTA drains its
// cp.async/syncthreads bubble, the other's warps keep the HMMA pipe fed.
#define BM 128
#define BN 128
#define BK 64
#define STG 3
#define CHUNKS (KDIM / BK)                 // 1008
#define A_STAGE (BM * BK * 2)              // 16384 B
#define B_STAGE (BN * BK * 2)              // 16384 B
#define STAGE_B (A_STAGE + B_STAGE)        // 32768 B
#define SMEM_GEMM (STG * STAGE_B)          // 98304 B per CTA (x2 CTAs = 192KB/SM)

// smem offset for logical (row, kc 16B-chunk of 8): SW128-style swizzle on 128B rows
__device__ __forceinline__ uint32_t sw_off(int row, int kc) {
    return (uint32_t)(row * 128 + ((kc ^ (row & 7)) << 4));
}

__device__ __forceinline__ void load_stage(uint32_t sA, uint32_t sB,
                                           const __half* __restrict__ gA,
                                           const __half* __restrict__ gB,
                                           int kOffHalf, int tid) {
    #pragma unroll
    for (int j = 0; j < 4; j++) {   // A: 128 rows x 8 chunks = 1024, 4/thread
        int idx = tid + j * 256;
        int row = idx >> 3, kc = idx & 7;
        const char* src = (const char*)(gA + (size_t)row * KDIM + kOffHalf) + kc * 16;
        cp_async16(sA + sw_off(row, kc), src);
    }
    #pragma unroll
    for (int j = 0; j < 4; j++) {   // B: 128 rows x 8 chunks = 1024, 4/thread
        int idx = tid + j * 256;
        int row = idx >> 3, kc = idx & 7;
        const char* src = (const char*)(gB + (size_t)row * KDIM + kOffHalf) + kc * 16;
        cp_async16(sB + sw_off(row, kc), src);
    }
}

__global__ void __launch_bounds__(256, 2) k_gemm(const float* __restrict__ bv) {
    extern __shared__ char smem[];
    uint32_t sbase = smem_u32(smem);
    int tid = threadIdx.x;
    int lane = tid & 31;
    int wid = tid >> 5;          // 0..7
    int wm = wid >> 2;           // 0..1  (64 rows each)
    int wn = wid & 3;            // 0..3  (32 cols each)
    int bn0 = blockIdx.x * BN;   // 16 n-blocks
    int bm0 = blockIdx.y * BM;   // 16 m-blocks

    const __half* gA = g_u  + (size_t)bm0 * KDIM;
    const __half* gB = g_bt + (size_t)bn0 * KDIM;

    // per-lane ldmatrix row/kc bases
    int g = lane >> 3, sub = lane & 7;
    int rowA_base = wm * 64 + ((g & 1) << 3) + sub;  // + mt*16
    int kcA_base  = g >> 1;                          // + ks*2
    int rowB_base = wn * 32 + ((g >> 1) << 3) + sub; // + q*16
    int kcB_base  = g & 1;                           // + ks*2

    float acc[4][4][4];
    #pragma unroll
    for (int i = 0; i < 4; i++)
        #pragma unroll
        for (int j = 0; j < 4; j++)
            #pragma unroll
            for (int t = 0; t < 4; t++) acc[i][j][t] = 0.f;

    // prologue: fill STG-1 stages
    #pragma unroll
    for (int s = 0; s < STG - 1; s++) {
        load_stage(sbase + s * STAGE_B, sbase + s * STAGE_B + A_STAGE, gA, gB, s * BK, tid);
        cp_commit();
    }

    int slot = 0;
    for (int k = 0; k < CHUNKS; k++) {
        cp_wait<STG - 2>();      // stage k's groups done (own thread)
        __syncthreads();         // stage-k data visible to all; refill slot free

        int kpre = k + STG - 1;
        if (kpre < CHUNKS) {
            int ps = slot + (STG - 1); if (ps >= STG) ps -= STG;
            load_stage(sbase + ps * STAGE_B, sbase + ps * STAGE_B + A_STAGE,
                       gA, gB, kpre * BK, tid);
        }
        cp_commit();

        uint32_t aS = sbase + slot * STAGE_B;
        uint32_t bS = aS + A_STAGE;
        #pragma unroll
        for (int ks = 0; ks < 4; ks++) {          // 4 x K16 steps cover BK=64
            uint32_t afr[4][4], bfr[2][4];
            #pragma unroll
            for (int q = 0; q < 2; q++) {
                int row = rowB_base + q * 16;
                ldsm_x4(bfr[q], bS + sw_off(row, ks * 2 + kcB_base));
            }
            #pragma unroll
            for (int mt = 0; mt < 4; mt++) {
                int row = rowA_base + mt * 16;
                ldsm_x4(afr[mt], aS + sw_off(row, ks * 2 + kcA_base));
            }
            #pragma unroll
            for (int mt = 0; mt < 4; mt++)
                #pragma unroll
                for (int nt = 0; nt < 4; nt++)
                    mma16816(acc[mt][nt], afr[mt], &bfr[nt >> 1][(nt & 1) * 2]);
        }
        if (++slot == STG) slot = 0;
    }

    // epilogue: bias + relu, write fp32 v
    int rlo = lane >> 2;         // 0..7
    int cpair = (lane & 3) * 2;  // 0,2,4,6
    #pragma unroll
    for (int mt = 0; mt < 4; mt++) {
        #pragma unroll
        for (int nt = 0; nt < 4; nt++) {
            int col = bn0 + wn * 32 + nt * 8 + cpair;
            float b0 = __ldg(bv + col), b1 = __ldg(bv + col + 1);
            int row0 = bm0 + wm * 64 + mt * 16 + rlo;
            float2 o0, o1;
            o0.x = fmaxf(acc[mt][nt][0] + b0, 0.f);
            o0.y = fmaxf(acc[mt][nt][1] + b1, 0.f);
            o1.x = fmaxf(acc[mt][nt][2] + b0, 0.f);
            o1.y = fmaxf(acc[mt][nt][3] + b1, 0.f);
            *reinterpret_cast<float2*>(g_v + (size_t)row0 * HIDDEN + col) = o0;
            *reinterpret_cast<float2*>(g_v + (size_t)(row0 + 8) * HIDDEN + col) = o1;
        }
    }
}

// ==================== kernel 4: head  out = v @ Wo + bo ====================
__global__ void k_final(const float* __restrict__ Wo, const float* __restrict__ bo,
                        float* __restrict__ out) {
    int n = blockIdx.x, tid = threadIdx.x;
    float acc[CLASSES] = {};
    const float* vrow = g_v + (size_t)n * HIDDEN;
    for (int h = tid; h < HIDDEN; h += 256) {
        float vv = vrow[h];
        const float* wrow = Wo + (size_t)h * CLASSES;
        #pragma unroll
        for (int c = 0; c < CLASSES; c++) acc[c] = fmaf(vv, wrow[c], acc[c]);
    }
    #pragma unroll
    for (int c = 0; c < CLASSES; c++)
        #pragma unroll
        for (int o = 16; o > 0; o >>= 1)
            acc[c] += __shfl_xor_sync(0xffffffffu, acc[c], o);
    __shared__ float part[8][CLASSES];
    if ((tid & 31) == 0) {
        #pragma unroll
        for (int c = 0; c < CLASSES; c++) part[tid >> 5][c] = acc[c];
    }
    __syncthreads();
    if (tid < CLASSES) {
        float s = 0.f;
        #pragma unroll
        for (int w = 0; w < 8; w++) s += part[w][tid];
        out[(size_t)n * CLASSES + tid] = s + bo[tid];
    }
}

// ==================== launch ====================
extern "C" void kernel_launch(void* const* d_in, const int* in_sizes, int n_in,
                              void* d_out, int out_size) {
    const float* x  = (const float*)d_in[0];
    const float* Wu = (const float*)d_in[1];
    const float* bu = (const float*)d_in[2];
    const float* Wv = (const float*)d_in[3];
    const float* bv = (const float*)d_in[4];
    const float* Wo = (const float*)d_in[5];
    const float* bo = (const float*)d_in[6];
    float* out = (float*)d_out;

    cudaFuncSetAttribute(k_gemm, cudaFuncAttributeMaxDynamicSharedMemorySize, SMEM_GEMM);

    k_transpose_x<<<(N_SAMPLES * D_FEAT + 255) / 256, 256>>>(x);
    k_prep<<<P_PAIRS + CONV_BLOCKS, 256>>>(Wu, bu, Wv);
    k_gemm<<<dim3(HIDDEN / BN, N_SAMPLES / BM), 256, SMEM_GEMM>>>(bv);
    k_final<<<N_SAMPLES, 256>>>(Wo, bo, out);
}

// round 6
// speedup vs baseline: 1.2658x; 1.2658x over previous
#include <cuda_runtime.h>
#include <cuda_fp16.h>
#include <cstdint>

// Problem dims
#define N_SAMPLES 2048
#define D_FEAT    64
#define P_PAIRS   2016
#define INNER     32
#define KDIM      64512   // P_PAIRS * INNER
#define HIDDEN    2048
#define CLASSES   10

// GEMM tiling
#define BM 128
#define BN 256
#define BK 64
#define STG 4
#define CHUNKS (KDIM / BK)                 // 1008
#define A_STAGE (BM * 128)                 // 16384 B (128 rows x 128B)
#define B_STAGE (BN * 128)                 // 32768 B (256 rows x 128B)
#define STAGE_B (A_STAGE + B_STAGE)        // 49152 B
#define OFF_MBAR (STG * STAGE_B)           // 196608
#define SMEM_GEMM (OFF_MBAR + 64)

// -------------------- scratch (device globals; no allocation) --------------------
// g_u tiled:  [mb(16)][c(1008)][row(128)][kc(8, swizzled)] of 16B units -> one A stage contiguous
// g_bt tiled: [nb(8)][c(1008)][row(256)][kc(8, swizzled)] of 16B units -> one B stage contiguous
__device__ __half g_u [(size_t)N_SAMPLES * KDIM];
__device__ __half g_bt[(size_t)HIDDEN    * KDIM];
__device__ float  g_v [(size_t)N_SAMPLES * HIDDEN];
__device__ float  g_xT[(size_t)D_FEAT * N_SAMPLES];

// -------------------- helpers --------------------
__device__ __forceinline__ uint32_t smem_u32(const void* p) {
    return (uint32_t)__cvta_generic_to_shared(p);
}
__device__ __forceinline__ void mbar_init(uint32_t addr, uint32_t count) {
    asm volatile("mbarrier.init.shared.b64 [%0], %1;" :: "r"(addr), "r"(count) : "memory");
}
__device__ __forceinline__ void mbar_expect_tx(uint32_t addr, uint32_t bytes) {
    asm volatile("mbarrier.arrive.expect_tx.shared.b64 _, [%0], %1;"
                 :: "r"(addr), "r"(bytes) : "memory");
}
__device__ __forceinline__ void mbar_arrive(uint32_t addr) {
    asm volatile("mbarrier.arrive.shared.b64 _, [%0];" :: "r"(addr) : "memory");
}
__device__ __forceinline__ void mbar_wait(uint32_t addr, uint32_t parity) {
    uint32_t done;
    asm volatile(
        "{\n\t.reg .pred p;\n\t"
        "mbarrier.try_wait.parity.acquire.cta.shared::cta.b64 p, [%1], %2;\n\t"
        "selp.b32 %0, 1, 0, p;\n\t}"
        : "=r"(done) : "r"(addr), "r"(parity) : "memory");
    if (!done) {
        asm volatile(
            "{\n\t.reg .pred P1;\n\t"
            "W_%=:\n\t"
            "mbarrier.try_wait.parity.acquire.cta.shared::cta.b64 P1, [%0], %1, 0x989680;\n\t"
            "@P1 bra.uni D_%=;\n\t"
            "bra.uni W_%=;\n\t"
            "D_%=:\n\t}"
            :: "r"(addr), "r"(parity) : "memory");
    }
}
// bulk copy: one instruction moves `bytes` gmem->smem via TMA engine (sm_90 base ISA)
__device__ __forceinline__ void bulk_g2s(uint32_t dstSmem, const void* srcGmem,
                                         uint32_t bytes, uint32_t mbar) {
    asm volatile(
        "cp.async.bulk.shared::cluster.global.mbarrier::complete_tx::bytes [%0], [%1], %2, [%3];"
        :: "r"(dstSmem), "l"(srcGmem), "r"(bytes), "r"(mbar) : "memory");
}
__device__ __forceinline__ void ldsm_x4(uint32_t* r, uint32_t addr) {
    asm volatile("ldmatrix.sync.aligned.m8n8.x4.shared.b16 {%0,%1,%2,%3}, [%4];"
                 : "=r"(r[0]), "=r"(r[1]), "=r"(r[2]), "=r"(r[3]) : "r"(addr));
}
__device__ __forceinline__ void mma16816(float* c, const uint32_t* a, const uint32_t* b) {
    asm volatile(
        "mma.sync.aligned.m16n8k16.row.col.f32.f16.f16.f32 "
        "{%0,%1,%2,%3}, {%4,%5,%6,%7}, {%8,%9}, {%0,%1,%2,%3};"
        : "+f"(c[0]), "+f"(c[1]), "+f"(c[2]), "+f"(c[3])
        : "r"(a[0]), "r"(a[1]), "r"(a[2]), "r"(a[3]), "r"(b[0]), "r"(b[1]));
}
// smem offset for logical (row, kc 16B-unit of 8) within a 128B-row tile
__device__ __forceinline__ uint32_t sw_off(int row, int kc) {
    return (uint32_t)(row * 128 + ((kc ^ (row & 7)) << 4));
}

// ==================== kernel 1: transpose x ====================
__global__ void k_transpose_x(const float* __restrict__ x) {
    int idx = blockIdx.x * blockDim.x + threadIdx.x;
    if (idx < N_SAMPLES * D_FEAT) {
        int n = idx >> 6, d = idx & 63;
        g_xT[(size_t)d * N_SAMPLES + n] = x[idx];
    }
}

// ==================== kernel 2 (fused): pairwise MLP + Wv transpose/convert ====================
// conv part: 64-n x 32-k tiles; each thread emits one 16B unit into swizzled g_bt
#define CONV_BLOCKS ((HIDDEN / 64) * (KDIM / 32))   // 32 * 2016

__global__ void k_prep(const float* __restrict__ Wu, const float* __restrict__ bu,
                       const float* __restrict__ Wv) {
    int tid = threadIdx.x;
    if (blockIdx.x < P_PAIRS) {
        int p = blockIdx.x;
        int a = 0, rem = p;
        while (rem >= (D_FEAT - 1 - a)) { rem -= (D_FEAT - 1 - a); a++; }
        int b = a + 1 + rem;

        __shared__ float w0[INNER], w1[INNER], bb[INNER];
        if (tid < INNER) {
            w0[tid] = Wu[(size_t)p * 2 * INNER + tid];
            w1[tid] = Wu[(size_t)p * 2 * INNER + INNER + tid];
            bb[tid] = bu[(size_t)p * INNER + tid];
        }
        __syncthreads();

        int c = p >> 1;        // k-chunk (64 halves)
        int h = p & 1;         // which half of the 128B row
        uint4* g_u_u4 = reinterpret_cast<uint4*>(g_u);
        const float* xa = g_xT + (size_t)a * N_SAMPLES;
        const float* xb = g_xT + (size_t)b * N_SAMPLES;
        for (int n = tid; n < N_SAMPLES; n += blockDim.x) {
            float va = xa[n], vb = xb[n];
            __half2 outv[INNER / 2];
            #pragma unroll
            for (int i = 0; i < INNER; i += 2) {
                float r0 = fmaf(va, w0[i],     fmaf(vb, w1[i],     bb[i]));
                float r1 = fmaf(va, w0[i + 1], fmaf(vb, w1[i + 1], bb[i + 1]));
                outv[i / 2] = __floats2half2_rn(fmaxf(r0, 0.f), fmaxf(r1, 0.f));
            }
            const uint4* src = reinterpret_cast<const uint4*>(outv);
            int mb = n >> 7, row = n & 127;
            size_t base8 = ((size_t)(mb * CHUNKS + c) * 128 + row) * 8;
            #pragma unroll
            for (int q = 0; q < 4; q++) {
                int kc = h * 4 + q;
                g_u_u4[base8 + (kc ^ (row & 7))] = src[q];
            }
        }
    } else {
        int bid = blockIdx.x - P_PAIRS;
        int nBlocks = HIDDEN / 64;            // 32
        int nt0 = (bid % nBlocks) * 64;       // HIDDEN tile (64 wide)
        int kt0 = (bid / nBlocks) * 32;       // KDIM tile (32 deep)
        __shared__ float tile[32][65];
        // load Wv[kt0..kt0+32)[nt0..nt0+64) coalesced
        #pragma unroll
        for (int pass = 0; pass < 8; pass++) {
            int idx = tid + pass * 256;       // 2048 elems
            int kl = idx >> 6, nl = idx & 63;
            tile[kl][nl] = Wv[(size_t)(kt0 + kl) * HIDDEN + nt0 + nl];
        }
        __syncthreads();
        // each thread packs 8 consecutive k for one n -> one 16B unit
        int nl = tid >> 2, uq = tid & 3;      // 64 n x 4 units
        __half hp[8];
        #pragma unroll
        for (int j = 0; j < 8; j++) hp[j] = __float2half(tile[uq * 8 + j][nl]);
        int n = nt0 + nl;
        int nb = n >> 8, rowB = n & 255;
        int c = kt0 >> 6;                      // kt0 is 32-aligned; which 64-chunk
        int kcq = ((kt0 & 63) >> 3) + uq;      // 0..3 or 4..7
        size_t unit = ((size_t)(nb * CHUNKS + c) * 256 + rowB) * 8 + (kcq ^ (rowB & 7));
        reinterpret_cast<uint4*>(g_bt)[unit] = *reinterpret_cast<uint4*>(hp);
    }
}

// ==================== kernel 3: big GEMM v = relu(u @ Wv + bv) ====================
// Bulk-TMA producer (warp0 lane0), 16 consumer warps, mbarrier pipeline,
// no __syncthreads in mainloop: warps progress independently.
__global__ void __launch_bounds__(512, 1) k_gemm(const float* __restrict__ bv) {
    extern __shared__ char smem[];
    uint32_t sbase = smem_u32(smem);
    int tid = threadIdx.x;
    int lane = tid & 31;
    int wid = tid >> 5;          // 0..15
    int wm = wid >> 3;           // 0..1  (64 rows each)
    int wn = wid & 7;            // 0..7  (32 cols each)
    int nb = blockIdx.x;         // 8 n-blocks
    int mb = blockIdx.y;         // 16 m-blocks

    const char* gA = (const char*)g_u  + (size_t)mb * CHUNKS * A_STAGE;
    const char* gB = (const char*)g_bt + (size_t)nb * CHUNKS * B_STAGE;

    uint32_t mfull = sbase + OFF_MBAR;        // 4 x 8B
    uint32_t mempty = sbase + OFF_MBAR + 32;  // 4 x 8B
    if (tid == 0) {
        #pragma unroll
        for (int s = 0; s < STG; s++) {
            mbar_init(mfull + s * 8, 1);      // producer expect_tx arrive
            mbar_init(mempty + s * 8, 16);    // one arrive per consumer warp
        }
    }
    __syncthreads();

    // prologue: fill stages 0..STG-2
    if (tid == 0) {
        #pragma unroll
        for (int s = 0; s < STG - 1; s++) {
            mbar_expect_tx(mfull + s * 8, STAGE_B);
            bulk_g2s(sbase + s * STAGE_B,           gA + (size_t)s * A_STAGE, A_STAGE, mfull + s * 8);
            bulk_g2s(sbase + s * STAGE_B + A_STAGE, gB + (size_t)s * B_STAGE, B_STAGE, mfull + s * 8);
        }
    }

    // per-lane ldmatrix row/kc bases
    int g = lane >> 3, sub = lane & 7;
    int rowA_base = wm * 64 + ((g & 1) << 3) + sub;  // + mt*16
    int kcA_base  = g >> 1;                          // + ks*2
    int rowB_base = wn * 32 + ((g >> 1) << 3) + sub; // + q*16
    int kcB_base  = g & 1;                           // + ks*2

    float acc[4][4][4];
    #pragma unroll
    for (int i = 0; i < 4; i++)
        #pragma unroll
        for (int j = 0; j < 4; j++)
            #pragma unroll
            for (int t = 0; t < 4; t++) acc[i][j][t] = 0.f;

    for (int k = 0; k < CHUNKS; k++) {
        int slot = k & 3;
        // producer: warp 0 refills stage k+STG-1
        if (wid == 0) {
            int kp = k + STG - 1;
            if (kp < CHUNKS) {
                int sp = kp & 3;
                if (kp >= STG) mbar_wait(mempty + sp * 8, ((kp >> 2) + 1) & 1);
                if (lane == 0) {
                    mbar_expect_tx(mfull + sp * 8, STAGE_B);
                    bulk_g2s(sbase + sp * STAGE_B,           gA + (size_t)kp * A_STAGE, A_STAGE, mfull + sp * 8);
                    bulk_g2s(sbase + sp * STAGE_B + A_STAGE, gB + (size_t)kp * B_STAGE, B_STAGE, mfull + sp * 8);
                }
            }
        }

        mbar_wait(mfull + slot * 8, (k >> 2) & 1);

        uint32_t aS = sbase + slot * STAGE_B;
        uint32_t bS = aS + A_STAGE;
        #pragma unroll
        for (int ks = 0; ks < 4; ks++) {          // 4 x K16 steps cover BK=64
            uint32_t afr[4][4], bfr[2][4];
            #pragma unroll
            for (int q = 0; q < 2; q++) {
                int row = rowB_base + q * 16;
                ldsm_x4(bfr[q], bS + sw_off(row, ks * 2 + kcB_base));
            }
            #pragma unroll
            for (int mt = 0; mt < 4; mt++) {
                int row = rowA_base + mt * 16;
                ldsm_x4(afr[mt], aS + sw_off(row, ks * 2 + kcA_base));
            }
            #pragma unroll
            for (int mt = 0; mt < 4; mt++)
                #pragma unroll
                for (int nt = 0; nt < 4; nt++)
                    mma16816(acc[mt][nt], afr[mt], &bfr[nt >> 1][(nt & 1) * 2]);
        }
        if (lane == 0) mbar_arrive(mempty + slot * 8);   // release: orders ldmatrix reads
    }

    // epilogue: bias + relu, write fp32 v
    int rlo = lane >> 2;
    int cpair = (lane & 3) * 2;
    int bn0 = nb * BN, bm0 = mb * BM;
    #pragma unroll
    for (int mt = 0; mt < 4; mt++) {
        #pragma unroll
        for (int nt = 0; nt < 4; nt++) {
            int col = bn0 + wn * 32 + nt * 8 + cpair;
            float b0 = __ldg(bv + col), b1 = __ldg(bv + col + 1);
            int row0 = bm0 + wm * 64 + mt * 16 + rlo;
            float2 o0, o1;
            o0.x = fmaxf(acc[mt][nt][0] + b0, 0.f);
            o0.y = fmaxf(acc[mt][nt][1] + b1, 0.f);
            o1.x = fmaxf(acc[mt][nt][2] + b0, 0.f);
            o1.y = fmaxf(acc[mt][nt][3] + b1, 0.f);
            *reinterpret_cast<float2*>(g_v + (size_t)row0 * HIDDEN + col) = o0;
            *reinterpret_cast<float2*>(g_v + (size_t)(row0 + 8) * HIDDEN + col) = o1;
        }
    }
}

// ==================== kernel 4: head  out = v @ Wo + bo ====================
__global__ void k_final(const float* __restrict__ Wo, const float* __restrict__ bo,
                        float* __restrict__ out) {
    int n = blockIdx.x, tid = threadIdx.x;
    float acc[CLASSES] = {};
    const float* vrow = g_v + (size_t)n * HIDDEN;
    for (int h = tid; h < HIDDEN; h += 256) {
        float vv = vrow[h];
        const float* wrow = Wo + (size_t)h * CLASSES;
        #pragma unroll
        for (int c = 0; c < CLASSES; c++) acc[c] = fmaf(vv, wrow[c], acc[c]);
    }
    #pragma unroll
    for (int c = 0; c < CLASSES; c++)
        #pragma unroll
        for (int o = 16; o > 0; o >>= 1)
            acc[c] += __shfl_xor_sync(0xffffffffu, acc[c], o);
    __shared__ float part[8][CLASSES];
    if ((tid & 31) == 0) {
        #pragma unroll
        for (int c = 0; c < CLASSES; c++) part[tid >> 5][c] = acc[c];
    }
    __syncthreads();
    if (tid < CLASSES) {
        float s = 0.f;
        #pragma unroll
        for (int w = 0; w < 8; w++) s += part[w][tid];
        out[(size_t)n * CLASSES + tid] = s + bo[tid];
    }
}

// ==================== launch ====================
extern "C" void kernel_launch(void* const* d_in, const int* in_sizes, int n_in,
                              void* d_out, int out_size) {
    const float* x  = (const float*)d_in[0];
    const float* Wu = (const float*)d_in[1];
    const float* bu = (const float*)d_in[2];
    const float* Wv = (const float*)d_in[3];
    const float* bv = (const float*)d_in[4];
    const float* Wo = (const float*)d_in[5];
    const float* bo = (const float*)d_in[6];
    float* out = (float*)d_out;

    cudaFuncSetAttribute(k_gemm, cudaFuncAttributeMaxDynamicSharedMemorySize, SMEM_GEMM);

    k_transpose_x<<<(N_SAMPLES * D_FEAT + 255) / 256, 256>>>(x);
    k_prep<<<P_PAIRS + CONV_BLOCKS, 256>>>(Wu, bu, Wv);
    k_gemm<<<dim3(HIDDEN / BN, N_SAMPLES / BM), 512, SMEM_GEMM>>>(bv);
    k_final<<<N_SAMPLES, 256>>>(Wo, bo, out);
}